// round 12
// baseline (speedup 1.0000x reference)
#include <cuda_runtime.h>
#include <math.h>

// Problem constants (fixed shapes from reference)
#define BB   16      // batch
#define SS   128     // steps / nodes
#define TT   160     // sentence length
#define HH   512     // hidden
#define EE   512     // embed
#define RDIM 128     // relation embed dim
#define VV   32000   // vocab

// -------- device scratch (no allocations allowed) --------
__device__ __align__(16) float g_h[2][2][BB][HH];   // [parity][layer][b][k]
__device__ __align__(16) float g_c[2][2][BB][HH];
__device__ unsigned long long g_amax[SS][BB];       // encoded (value, index) per step
__device__ int g_mask_is_byte;

// -------- packed fp32x2 FMA (Blackwell) --------
static __device__ __forceinline__ unsigned long long ffma2(unsigned long long a,
                                                           unsigned long long b,
                                                           unsigned long long c) {
    unsigned long long d;
    asm("fma.rn.f32x2 %0, %1, %2, %3;" : "=l"(d) : "l"(a), "l"(b), "l"(c));
    return d;
}
static __device__ __forceinline__ float2 upk(unsigned long long v) {
    float2 r;
    asm("mov.b64 {%0, %1}, %2;" : "=f"(r.x), "=f"(r.y) : "l"(v));
    return r;
}
static __device__ __forceinline__ float wsum(float s) {
#pragma unroll
    for (int o = 16; o; o >>= 1) s += __shfl_xor_sync(0xffffffffu, s, o);
    return s;
}
static __device__ __forceinline__ double sigd(double x) { return 1.0 / (1.0 + exp(-x)); }

// ---------------------------------------------------------------------------
// init: zero argmax slots, tile hiddens into (h,c) for both layers (parity 0),
// and detect whether teacher_mask arrived as 1-byte bool or int32.
// ---------------------------------------------------------------------------
__global__ void init_kernel(const float* __restrict__ hiddens,
                            const unsigned char* __restrict__ tmask) {
    int tid = threadIdx.x;
    for (int i = tid; i < SS * BB; i += blockDim.x)
        ((unsigned long long*)g_amax)[i] = 0ull;
    float* hf = &g_h[0][0][0][0];
    float* cf = &g_c[0][0][0][0];
    for (int i = tid; i < BB * HH; i += blockDim.x) {
        float v = hiddens[i];
        hf[i] = v; hf[BB * HH + i] = v;
        cf[i] = v; cf[BB * HH + i] = v;
    }
    __shared__ int sflag;
    if (tid == 0) sflag = 0;
    __syncthreads();
    // int32 little-endian 0/1 => bytes at i%4!=0 are all zero.
    // bool8 => those byte positions carry real 0/1 mask values (~half ones).
    int f = 0;
    for (int i = tid; i < BB * SS; i += blockDim.x)
        if ((i & 3) && tmask[i]) f = 1;
    if (f) atomicOr(&sflag, 1);
    __syncthreads();
    if (tid == 0) g_mask_is_byte = sflag;
}

// ---------------------------------------------------------------------------
// LSTM layer 0: one warp per (b, cell j). Input x = [rel_emb[rel], word(640)],
// word chosen from teacher (gold) / previous argmax / SOS at t==0.
// ---------------------------------------------------------------------------
__global__ void lstm0_kernel(int t,
                             const float* __restrict__ w_ih,
                             const float* __restrict__ w_hh,
                             const float* __restrict__ bias,
                             const float* __restrict__ rel_emb,
                             const float* __restrict__ embed,
                             const int* __restrict__ relations,
                             const int* __restrict__ gold,
                             const unsigned char* __restrict__ tmask) {
    int gw = blockIdx.x * (blockDim.x >> 5) + (threadIdx.x >> 5);
    int lane = threadIdx.x & 31;
    int b = gw >> 9;
    int j = gw & 511;
    int p = t & 1;

    int widx;
    if (t == 0) {
        widx = 1;  // SOS / null token
    } else {
        int m;
        if (g_mask_is_byte) m = tmask[b * SS + t];
        else                m = ((const int*)tmask)[b * SS + t];
        if (m) widx = gold[b * SS + t - 1];
        else   widx = (int)(0xFFFFFFFFu - (unsigned)(g_amax[t - 1][b] & 0xFFFFFFFFull));
    }
    int rel = relations[b * SS + t];

    typedef ulonglong2 u2;
    const u2* rp = (const u2*)(rel_emb + (long)rel * RDIM);
    const u2* wp = (const u2*)(embed + (long)widx * EE);
    const u2* hp = (const u2*)(&g_h[p][0][b][0]);
    u2 xr = rp[lane];
    u2 xw[4], xh[4];
#pragma unroll
    for (int i = 0; i < 4; i++) xw[i] = wp[lane + 32 * i];
#pragma unroll
    for (int i = 0; i < 4; i++) xh[i] = hp[lane + 32 * i];

    float gate[4];
#pragma unroll
    for (int gi = 0; gi < 4; gi++) {
        int r = j + gi * 512;
        const u2* wi = (const u2*)(w_ih + (long)r * (RDIM + EE));
        const u2* wh = (const u2*)(w_hh + (long)r * HH);
        unsigned long long a0 = 0ull, a1 = 0ull;
        u2 w0 = wi[lane];
        a0 = ffma2(w0.x, xr.x, a0); a1 = ffma2(w0.y, xr.y, a1);
#pragma unroll
        for (int i = 0; i < 4; i++) {
            u2 w = wi[32 + lane + 32 * i];
            a0 = ffma2(w.x, xw[i].x, a0); a1 = ffma2(w.y, xw[i].y, a1);
        }
#pragma unroll
        for (int i = 0; i < 4; i++) {
            u2 w = wh[lane + 32 * i];
            a0 = ffma2(w.x, xh[i].x, a0); a1 = ffma2(w.y, xh[i].y, a1);
        }
        float2 f0 = upk(a0), f1 = upk(a1);
        gate[gi] = wsum((f0.x + f0.y) + (f1.x + f1.y)) + bias[r];
    }
    if (lane == 0) {
        // double-precision nonlinearities: fast-math-proof, ~correctly rounded
        double i_ = sigd((double)gate[0]);
        double f_ = sigd((double)gate[1]);
        double g_ = tanh((double)gate[2]);
        double o_ = sigd((double)gate[3]);
        float cold = g_c[p][0][b][j];
        float cnew = (float)(f_ * (double)cold + i_ * g_);
        float hnew = (float)(o_ * tanh((double)cnew));
        g_c[p ^ 1][0][b][j] = cnew;
        g_h[p ^ 1][0][b][j] = hnew;
    }
}

// ---------------------------------------------------------------------------
// LSTM layer 1: input = layer0's fresh h (parity p^1), state = layer1 (parity p).
// ---------------------------------------------------------------------------
__global__ void lstm1_kernel(int t,
                             const float* __restrict__ w_ih,
                             const float* __restrict__ w_hh,
                             const float* __restrict__ bias) {
    int gw = blockIdx.x * (blockDim.x >> 5) + (threadIdx.x >> 5);
    int lane = threadIdx.x & 31;
    int b = gw >> 9;
    int j = gw & 511;
    int p = t & 1;

    typedef ulonglong2 u2;
    const u2* xp = (const u2*)(&g_h[p ^ 1][0][b][0]);
    const u2* hp = (const u2*)(&g_h[p][1][b][0]);
    u2 xx[4], xh[4];
#pragma unroll
    for (int i = 0; i < 4; i++) xx[i] = xp[lane + 32 * i];
#pragma unroll
    for (int i = 0; i < 4; i++) xh[i] = hp[lane + 32 * i];

    float gate[4];
#pragma unroll
    for (int gi = 0; gi < 4; gi++) {
        int r = j + gi * 512;
        const u2* wi = (const u2*)(w_ih + (long)r * HH);
        const u2* wh = (const u2*)(w_hh + (long)r * HH);
        unsigned long long a0 = 0ull, a1 = 0ull;
#pragma unroll
        for (int i = 0; i < 4; i++) {
            u2 w = wi[lane + 32 * i];
            a0 = ffma2(w.x, xx[i].x, a0); a1 = ffma2(w.y, xx[i].y, a1);
        }
#pragma unroll
        for (int i = 0; i < 4; i++) {
            u2 w = wh[lane + 32 * i];
            a0 = ffma2(w.x, xh[i].x, a0); a1 = ffma2(w.y, xh[i].y, a1);
        }
        float2 f0 = upk(a0), f1 = upk(a1);
        gate[gi] = wsum((f0.x + f0.y) + (f1.x + f1.y)) + bias[r];
    }
    if (lane == 0) {
        double i_ = sigd((double)gate[0]);
        double f_ = sigd((double)gate[1]);
        double g_ = tanh((double)gate[2]);
        double o_ = sigd((double)gate[3]);
        float cold = g_c[p][1][b][j];
        float cnew = (float)(f_ * (double)cold + i_ * g_);
        float hnew = (float)(o_ * tanh((double)cnew));
        g_c[p ^ 1][1][b][j] = cnew;
        g_h[p ^ 1][1][b][j] = hnew;
    }
}

// ---------------------------------------------------------------------------
// Vocab projection + argmax. grid = 16 batches * 125 row-blocks; each warp
// computes 32 rows (512-length dots, fp32x2 FMA, warp-butterfly reduce).
// Key encoding: (orderable float << 32) | (0xFFFFFFFF - index) so atomicMax
// picks max value, lowest index on ties (matches jnp.argmax).
// ---------------------------------------------------------------------------
__global__ void outproj_kernel(int t,
                               const float* __restrict__ out_w,
                               const float* __restrict__ out_b) {
    int b  = blockIdx.x / 125;
    int rb = blockIdx.x % 125;
    int warp = threadIdx.x >> 5, lane = threadIdx.x & 31;

    typedef ulonglong2 u2;
    const u2* hp = (const u2*)(&g_h[(t + 1) & 1][1][b][0]);
    u2 h[4];
#pragma unroll
    for (int i = 0; i < 4; i++) h[i] = hp[lane + 32 * i];

    int v0 = rb * 256 + warp * 32;
    float bestv = -1e30f;
    int besti = v0;
#pragma unroll 2
    for (int r = 0; r < 32; r++) {
        int v = v0 + r;
        const u2* wp = (const u2*)(out_w + (long)v * HH);
        unsigned long long a0 = 0ull, a1 = 0ull;
#pragma unroll
        for (int i = 0; i < 4; i++) {
            u2 w = wp[lane + 32 * i];
            a0 = ffma2(w.x, h[i].x, a0); a1 = ffma2(w.y, h[i].y, a1);
        }
        float2 f0 = upk(a0), f1 = upk(a1);
        float s = wsum((f0.x + f0.y) + (f1.x + f1.y)) + out_b[v];
        if (s > bestv) { bestv = s; besti = v; }  // strict > keeps first index on ties
    }
    unsigned u = __float_as_uint(bestv);
    u = (u & 0x80000000u) ? ~u : (u | 0x80000000u);
    unsigned long long key =
        ((unsigned long long)u << 32) |
        (unsigned long long)(0xFFFFFFFFu - (unsigned)besti);

    __shared__ unsigned long long sk[8];
    if (lane == 0) sk[warp] = key;
    __syncthreads();
    if (threadIdx.x == 0) {
        unsigned long long m = sk[0];
#pragma unroll
        for (int i = 1; i < 8; i++) if (sk[i] > m) m = sk[i];
        atomicMax(&g_amax[t][b], m);
    }
}

// ---------------------------------------------------------------------------
// finalize: out[b,t,:] = transfer_w[argmax] for t<128, else sentences[b,t,:].
// (soft + stopgrad(hard - soft) == hard up to ~1e-9 relative rounding.)
// ---------------------------------------------------------------------------
__global__ void finalize_kernel(const float* __restrict__ sentences,
                                const float* __restrict__ transfer_w,
                                float* __restrict__ out) {
    int bt = blockIdx.x;
    int b = bt / TT;
    int t = bt - b * TT;
    const float4* src;
    if (t < SS) {
        int idx = (int)(0xFFFFFFFFu - (unsigned)(g_amax[t][b] & 0xFFFFFFFFull));
        src = (const float4*)(transfer_w + (long)idx * EE);
    } else {
        src = (const float4*)(sentences + (long)bt * EE);
    }
    ((float4*)(out + (long)bt * EE))[threadIdx.x] = src[threadIdx.x];
}

// ---------------------------------------------------------------------------
extern "C" void kernel_launch(void* const* d_in, const int* in_sizes, int n_in,
                              void* d_out, int out_size) {
    const float* hiddens    = (const float*)d_in[0];
    const float* sentences  = (const float*)d_in[1];
    const int*   relations  = (const int*)d_in[2];
    const int*   gold       = (const int*)d_in[3];
    const unsigned char* tmask = (const unsigned char*)d_in[4];
    const float* embed      = (const float*)d_in[5];
    const float* rel_emb    = (const float*)d_in[6];
    const float* w_ih0      = (const float*)d_in[7];
    const float* w_hh0      = (const float*)d_in[8];
    const float* b0         = (const float*)d_in[9];
    const float* w_ih1      = (const float*)d_in[10];
    const float* w_hh1      = (const float*)d_in[11];
    const float* b1         = (const float*)d_in[12];
    const float* out_w      = (const float*)d_in[13];
    const float* out_b      = (const float*)d_in[14];
    const float* transfer_w = (const float*)d_in[15];

    init_kernel<<<1, 1024>>>(hiddens, tmask);
    for (int t = 0; t < SS; t++) {
        lstm0_kernel<<<1024, 256>>>(t, w_ih0, w_hh0, b0, rel_emb, embed,
                                    relations, gold, tmask);
        lstm1_kernel<<<1024, 256>>>(t, w_ih1, w_hh1, b1);
        outproj_kernel<<<2000, 256>>>(t, out_w, out_b);
    }
    finalize_kernel<<<BB * TT, 128>>>(sentences, transfer_w, (float*)d_out);
}

// round 13
// speedup vs baseline: 2.9917x; 2.9917x over previous
#include <cuda_runtime.h>
#include <math.h>

#define BB   16
#define SS   128
#define TT   160
#define HH   512
#define EE   512
#define RDIM 128
#define GRID 148
#define NTH  512
#define NWARP 16
#define TOTW (GRID * NWARP)   // 2368 warps

typedef unsigned long long ull;

// -------- device scratch (no allocations allowed) --------
__device__ __align__(16) float g_h[2][2][BB][HH];     // [parity][layer][b][k]
__device__ __align__(16) float g_c[2][2][BB][HH];
__device__ __align__(16) float g_part[9][2048][BB];   // gate partials [slab][gaterow][b]
__device__ ull      g_amax[SS][BB];
__device__ unsigned g_arrive;
__device__ int      g_mask_is_byte;

// -------- packed fp32x2 FMA (Blackwell) --------
static __device__ __forceinline__ ull ffma2(ull a, ull b, ull c) {
    ull d; asm("fma.rn.f32x2 %0, %1, %2, %3;" : "=l"(d) : "l"(a), "l"(b), "l"(c));
    return d;
}
static __device__ __forceinline__ float2 upk(ull v) {
    float2 r; asm("mov.b64 {%0, %1}, %2;" : "=f"(r.x), "=f"(r.y) : "l"(v));
    return r;
}
static __device__ __forceinline__ double sigd(double x) { return 1.0 / (1.0 + exp(-x)); }

// -------- software grid barrier (all 148 blocks resident: 1 block/SM) --------
static __device__ __forceinline__ void gsync() {
    __syncthreads();
    if (threadIdx.x == 0) {
        __threadfence();                       // fence.gpu -> CCTL.IVALL (L1 coherent)
        unsigned old  = atomicAdd(&g_arrive, 1u);
        unsigned need = (old / GRID + 1u) * GRID;
        while (*(volatile unsigned*)&g_arrive < need) { }
        __threadfence();
    }
    __syncthreads();
}

// ---------------------------------------------------------------------------
// 16-rows x 16-batch GEMM tile. lane = (row<<1)|khalf; each lane reads its
// row's 16B half of a 32B chunk per iter -> warp LDG = 16 rows x 32B,
// sector-exact, weights read once chip-wide. x via 2-address broadcast LDS.
// acc[b] packs (even-k, odd-k) partial sums as f32x2.
// ---------------------------------------------------------------------------
static __device__ __forceinline__ void gtile(const float* __restrict__ W, int wstride,
                                             int rowbase, int kw, int kx, int nc,
                                             const float* __restrict__ xs, int xst,
                                             ull acc[16]) {
    int lane = threadIdx.x & 31;
    const float* wr = W + (size_t)(rowbase + (lane >> 1)) * wstride + kw + (lane & 1) * 4;
    const float* xr = xs + kx + (lane & 1) * 4;
#pragma unroll 4
    for (int c = 0; c < nc; c++) {
        ulonglong2 w = *(const ulonglong2*)(wr + c * 8);
#pragma unroll
        for (int b = 0; b < 16; b++) {
            ulonglong2 x = *(const ulonglong2*)(xr + b * xst + c * 8);
            acc[b] = ffma2(w.x, x.x, acc[b]);
            acc[b] = ffma2(w.y, x.y, acc[b]);
        }
    }
}

// Reduce pair-lane accs to full row dots and store slab partials (even lanes write).
static __device__ __forceinline__ void store_part(int slab, int rowbase, ull acc[16]) {
    int lane = threadIdx.x & 31;
    float o[16];
#pragma unroll
    for (int b = 0; b < 16; b++) {
        float2 f = upk(acc[b]);
        float s = f.x + f.y;
        s += __shfl_xor_sync(0xffffffffu, s, 1);   // merge k-halves (deterministic)
        o[b] = s;
    }
    if (!(lane & 1)) {
        float4* d = (float4*)&g_part[slab][rowbase + (lane >> 1)][0];
        d[0] = make_float4(o[0],  o[1],  o[2],  o[3]);
        d[1] = make_float4(o[4],  o[5],  o[6],  o[7]);
        d[2] = make_float4(o[8],  o[9],  o[10], o[11]);
        d[3] = make_float4(o[12], o[13], o[14], o[15]);
    }
}

// Gate combine + fp64 nonlinearities; cells spread across all SMs.
static __device__ __forceinline__ void combine(int layer, int nslab, int p,
                                               const float* __restrict__ bias) {
    int cell = blockIdx.x * 56 + threadIdx.x;
    if (threadIdx.x < 56 && cell < BB * HH) {
        int b = cell & 15, j = cell >> 4;
        float gs[4];
#pragma unroll
        for (int gi = 0; gi < 4; gi++) {
            float s = bias[gi * HH + j];
            for (int sl = 0; sl < nslab; sl++) s += g_part[sl][gi * HH + j][b];
            gs[gi] = s;
        }
        double i_ = sigd((double)gs[0]);
        double f_ = sigd((double)gs[1]);
        double g_ = tanh((double)gs[2]);
        double o_ = sigd((double)gs[3]);
        float cold = g_c[p][layer][b][j];
        float cnew = (float)(f_ * (double)cold + i_ * g_);
        float hnew = (float)(o_ * tanh((double)cnew));
        g_c[p ^ 1][layer][b][j] = cnew;
        g_h[p ^ 1][layer][b][j] = hnew;
    }
}

// ---------------------------------------------------------------------------
__global__ void init_kernel(const float* __restrict__ hiddens,
                            const unsigned char* __restrict__ tmask) {
    int tid = threadIdx.x;
    if (tid == 0) g_arrive = 0u;
    for (int i = tid; i < SS * BB; i += blockDim.x) ((ull*)g_amax)[i] = 0ull;
    float* hf = &g_h[0][0][0][0];
    float* cf = &g_c[0][0][0][0];
    for (int i = tid; i < BB * HH; i += blockDim.x) {
        float v = hiddens[i];
        hf[i] = v; hf[BB * HH + i] = v;
        cf[i] = v; cf[BB * HH + i] = v;
    }
    __shared__ int sflag;
    if (tid == 0) sflag = 0;
    __syncthreads();
    int f = 0;   // int32 0/1 has zero bytes at i%4!=0; bool8 does not
    for (int i = tid; i < BB * SS; i += blockDim.x)
        if ((i & 3) && tmask[i]) f = 1;
    if (f) atomicOr(&sflag, 1);
    __syncthreads();
    if (tid == 0) g_mask_is_byte = sflag;
}

// ---------------------------------------------------------------------------
// Persistent kernel: full 128-step recurrence + finalize. 5 grid barriers/step.
// ---------------------------------------------------------------------------
extern "C" __global__ void __launch_bounds__(NTH, 1)
seq_kernel(const float* __restrict__ sentences, const int* __restrict__ relations,
           const int* __restrict__ gold, const unsigned char* __restrict__ tmask,
           const float* __restrict__ embed, const float* __restrict__ rel_emb,
           const float* __restrict__ w_ih0, const float* __restrict__ w_hh0,
           const float* __restrict__ b0,
           const float* __restrict__ w_ih1, const float* __restrict__ w_hh1,
           const float* __restrict__ b1,
           const float* __restrict__ out_w, const float* __restrict__ out_b,
           const float* __restrict__ transfer_w, float* __restrict__ out) {
    extern __shared__ float xs[];        // [16][1152] max (x tiles, block-local)
    __shared__ int sidx[32];             // [0:16) widx, [16:32) rel
    __shared__ ull sbest[16];
    int tid = threadIdx.x, blk = blockIdx.x;
    int warp = tid >> 5, lane = tid & 31;
    int wid2 = warp * GRID + blk;        // SM-spread global warp id

    for (int t = 0; t < SS; t++) {
        int p = t & 1;
        // ---- phase A: x0 = [rel(128) | word(512) | h0_prev(512)] ----
        if (tid < BB) {
            int b = tid, widx;
            if (t == 0) widx = 1;        // SOS / null token
            else {
                int m = g_mask_is_byte ? tmask[b * SS + t]
                                       : ((const int*)tmask)[b * SS + t];
                widx = m ? gold[b * SS + t - 1]
                         : (int)(0xFFFFFFFFu - (unsigned)(g_amax[t - 1][b] & 0xFFFFFFFFull));
            }
            sidx[b] = widx;
            sidx[16 + b] = relations[b * SS + t];
        }
        __syncthreads();
        for (int i = tid; i < BB * 288; i += NTH) {
            int b = i / 288, k4 = (i - b * 288) * 4;
            float4 v;
            if (k4 < RDIM)
                v = *(const float4*)(rel_emb + (size_t)sidx[16 + b] * RDIM + k4);
            else if (k4 < RDIM + EE)
                v = *(const float4*)(embed + (size_t)sidx[b] * EE + (k4 - RDIM));
            else
                v = *(const float4*)(&g_h[p][0][b][k4 - (RDIM + EE)]);
            *(float4*)(xs + b * 1152 + k4) = v;
        }
        __syncthreads();
        if (wid2 < 1152) {               // 128 rowgroups x 9 k-slabs(128)
            int rg = wid2 / 9, slab = wid2 - rg * 9;
            ull acc[16];
#pragma unroll
            for (int b = 0; b < 16; b++) acc[b] = 0ull;
            if (slab < 5) gtile(w_ih0, RDIM + EE, rg * 16, slab * 128,       slab * 128, 16, xs, 1152, acc);
            else          gtile(w_hh0, HH,        rg * 16, (slab - 5) * 128, slab * 128, 16, xs, 1152, acc);
            store_part(slab, rg * 16, acc);
        }
        gsync();
        combine(0, 9, p, b0);
        gsync();
        // ---- phase B: x1 = [h0_new(512) | h1_prev(512)] ----
        for (int i = tid; i < BB * 256; i += NTH) {
            int b = i >> 8, k4 = (i & 255) * 4;
            float4 v = (k4 < HH) ? *(const float4*)(&g_h[p ^ 1][0][b][k4])
                                 : *(const float4*)(&g_h[p][1][b][k4 - HH]);
            *(float4*)(xs + b * 1024 + k4) = v;
        }
        __syncthreads();
        if (wid2 < 1024) {               // 128 rowgroups x 8 k-slabs(128)
            int rg = wid2 >> 3, slab = wid2 & 7;
            ull acc[16];
#pragma unroll
            for (int b = 0; b < 16; b++) acc[b] = 0ull;
            if (slab < 4) gtile(w_ih1, HH, rg * 16, slab * 128,       slab * 128, 16, xs, 1024, acc);
            else          gtile(w_hh1, HH, rg * 16, (slab - 4) * 128, slab * 128, 16, xs, 1024, acc);
            store_part(slab, rg * 16, acc);
        }
        gsync();
        combine(1, 8, p, b1);
        gsync();
        // ---- phase C: outproj (2000 tasks, 16 rows x full k=512) + argmax ----
        if (tid < 16) sbest[tid] = 0ull;
        for (int i = tid; i < BB * 128; i += NTH) {
            int b = i >> 7, k4 = (i & 127) * 4;
            *(float4*)(xs + b * 512 + k4) = *(const float4*)(&g_h[p ^ 1][1][b][k4]);
        }
        __syncthreads();
        for (int tk = wid2; tk < 2000; tk += TOTW) {
            int rowbase = tk * 16;
            int row = rowbase + (lane >> 1);
            ull acc[16];
#pragma unroll
            for (int b = 0; b < 16; b++) acc[b] = 0ull;
            gtile(out_w, HH, rowbase, 0, 0, 64, xs, 512, acc);
            float bias = out_b[row];
            ull my = 0ull;
#pragma unroll
            for (int b = 0; b < 16; b++) {
                float2 f = upk(acc[b]);
                float s = f.x + f.y;
                s += __shfl_xor_sync(0xffffffffu, s, 1);   // merge k-halves
                s += bias;
                unsigned u = __float_as_uint(s);
                u = (u & 0x80000000u) ? ~u : (u | 0x80000000u);
                ull key = ((ull)u << 32) | (ull)(0xFFFFFFFFu - (unsigned)row);
#pragma unroll
                for (int off = 2; off <= 16; off <<= 1) {  // max over the 16 rows
                    ull o2 = __shfl_xor_sync(0xffffffffu, key, off);
                    if (o2 > key) key = o2;
                }
                if (lane == b) my = key;                   // lane b keeps batch b winner
            }
            if (lane < 16) atomicMax(&sbest[lane], my);
        }
        __syncthreads();
        if (tid < 16) atomicMax(&g_amax[t][tid], sbest[tid]);
        gsync();
    }

    // ---- finalize: out[b,t,:] = transfer_w[argmax] for t<128, else sentences ----
    for (int i = blk * NTH + tid; i < BB * TT * (EE / 4); i += GRID * NTH) {
        int k4 = (i & 127) * 4;
        int bt = i >> 7;
        int b = bt / TT, tt = bt - b * TT;
        float4 v;
        if (tt < SS) {
            int idx = (int)(0xFFFFFFFFu - (unsigned)(g_amax[tt][b] & 0xFFFFFFFFull));
            v = *(const float4*)(transfer_w + (size_t)idx * EE + k4);
        } else {
            v = *(const float4*)(sentences + (size_t)bt * EE + k4);
        }
        *(float4*)(out + (size_t)bt * EE + k4) = v;
    }
}

// ---------------------------------------------------------------------------
extern "C" void kernel_launch(void* const* d_in, const int* in_sizes, int n_in,
                              void* d_out, int out_size) {
    const float* hiddens    = (const float*)d_in[0];
    const float* sentences  = (const float*)d_in[1];
    const int*   relations  = (const int*)d_in[2];
    const int*   gold       = (const int*)d_in[3];
    const unsigned char* tmask = (const unsigned char*)d_in[4];
    const float* embed      = (const float*)d_in[5];
    const float* rel_emb    = (const float*)d_in[6];
    const float* w_ih0      = (const float*)d_in[7];
    const float* w_hh0      = (const float*)d_in[8];
    const float* b0         = (const float*)d_in[9];
    const float* w_ih1      = (const float*)d_in[10];
    const float* w_hh1      = (const float*)d_in[11];
    const float* b1         = (const float*)d_in[12];
    const float* out_w      = (const float*)d_in[13];
    const float* out_b      = (const float*)d_in[14];
    const float* transfer_w = (const float*)d_in[15];

    const int smem = BB * 1152 * sizeof(float);   // 73728 B dynamic
    static int configured = 0;
    cudaFuncSetAttribute(seq_kernel, cudaFuncAttributeMaxDynamicSharedMemorySize, smem);
    (void)configured;

    init_kernel<<<1, 1024>>>(hiddens, tmask);
    seq_kernel<<<GRID, NTH, smem>>>(sentences, relations, gold, tmask, embed, rel_emb,
                                    w_ih0, w_hh0, b0, w_ih1, w_hh1, b1,
                                    out_w, out_b, transfer_w, (float*)d_out);
}